// round 15
// baseline (speedup 1.0000x reference)
#include <cuda_runtime.h>
#include <cuda_bf16.h>
#include <cstdint>

// ───────────────────────── problem constants ─────────────────────────
constexpr int BATCH = 32;
constexpr int CH    = 256;     // C == D == K(gemm)
constexpr int KCODE = 1024;    // codebook size
constexpr int HWS   = 1024;    // H*W
constexpr int NPOS  = BATCH * HWS;                 // 32768 positions
constexpr long long TOT = (long long)NPOS * CH;    // 8388608 z_e elements
constexpr float BETA_W = 0.25f;
// bf16 single-product distance error margin; everything inside is re-decided
// EXACTLY in fp32 by repair. Flagged positions get a ~0ull sentinel in g_best
// so ONLY fp32-exact keys compete there.
constexpr float MARGIN = 0.75f;

typedef unsigned long long ull;

// smem layout for MMA kernel (bytes)
constexpr int SB_A  = 0;                  // A: 256 rows x 512B swizzled = 131072
constexpr int SB_B0 = 131072;             // B buf0: 64 rows x 512B      = 32768
constexpr int SB_B1 = 163840;             // B buf1                      = 32768
constexpr int SMEM_TOTAL = 196608;        // 192KB

// repair kernel smem: Es[64][256] + Xs[32][260] floats + sbest[32] u64
constexpr int RP_ES   = 64 * 256;                       // floats (uniform access)
constexpr int RP_XS   = 32 * 260;                       // floats (padded rows)
constexpr int RP_SMEM = (RP_ES + RP_XS) * 4 + 32 * 8;   // 99072 bytes

// ───────────────────────── device scratch ─────────────────────────
__device__ __align__(16) __nv_bfloat16 g_Zh[(size_t)NPOS * CH];  // [n][c] bf16
__device__ __align__(16) float         g_Zf[(size_t)NPOS * CH];  // [n][c] fp32
__device__ __align__(16) __nv_bfloat16 g_Eh[(size_t)KCODE * CH]; // [k][c] bf16
__device__ float  g_e2[KCODE];
__device__ int    g_counts[KCODE];
__device__ double g_partials[1024];
__device__ int    g_nflag;
__device__ int    g_done;
__device__ int    g_flag[NPOS];
__device__ unsigned long long g_best[NPOS];   // packed (ordmap(dist)<<32)|code

// ───────────────────────── PTX helpers ─────────────────────────
__device__ __forceinline__ uint32_t smem_u32(const void* p) {
    uint32_t a;
    asm("{ .reg .u64 t; cvta.to.shared.u64 t, %1; cvt.u32.u64 %0, t; }" : "=r"(a) : "l"(p));
    return a;
}
__device__ __forceinline__ void cp16(uint32_t dst, const void* src) {
    asm volatile("cp.async.cg.shared.global [%0], [%1], 16;" :: "r"(dst), "l"(src));
}
#define CP_COMMIT() asm volatile("cp.async.commit_group;" ::: "memory")
#define CP_WAIT0()  asm volatile("cp.async.wait_group 0;" ::: "memory")

__device__ __forceinline__ void ldsm_x4(uint32_t& r0, uint32_t& r1, uint32_t& r2,
                                        uint32_t& r3, uint32_t addr) {
    asm volatile("ldmatrix.sync.aligned.m8n8.x4.shared.b16 {%0,%1,%2,%3}, [%4];"
                 : "=r"(r0), "=r"(r1), "=r"(r2), "=r"(r3) : "r"(addr));
}
__device__ __forceinline__ void mma16816(float* d, const uint32_t* a, uint32_t b0, uint32_t b1) {
    asm volatile("mma.sync.aligned.m16n8k16.row.col.f32.bf16.bf16.f32 "
                 "{%0,%1,%2,%3}, {%4,%5,%6,%7}, {%8,%9}, {%0,%1,%2,%3};"
                 : "+f"(d[0]), "+f"(d[1]), "+f"(d[2]), "+f"(d[3])
                 : "r"(a[0]), "r"(a[1]), "r"(a[2]), "r"(a[3]), "r"(b0), "r"(b1));
}
__device__ __forceinline__ unsigned ordmap(float f) {
    unsigned u = __float_as_uint(f);
    return (u & 0x80000000u) ? ~u : (u | 0x80000000u);
}
__device__ __forceinline__ float unord(unsigned v) {
    v = (v & 0x80000000u) ? (v & 0x7FFFFFFFu) : ~v;
    return __uint_as_float(v);
}
__device__ __forceinline__ float f4_elem(const float4& v, int j) {
    switch (j) { case 0: return v.x; case 1: return v.y; case 2: return v.z; }
    return v.w;
}

// ───────────── kernel 1: transpose z_e + (fused) init plane ─────────────
// grid (32, 8, 33): z<32 = transpose planes; z==32 = init work.
__global__ void convert_init_kernel(const float* __restrict__ z_e,
                                    const float* __restrict__ embed) {
    if (blockIdx.z == BATCH) {
        int bid = blockIdx.y * gridDim.x + blockIdx.x;          // 0..255
        int tid = threadIdx.y * 32 + threadIdx.x;
        int gid = bid * 256 + tid;                              // 0..65535
        int warp = gid >> 5, lane = gid & 31;
        if (warp < KCODE) {
            const float4* row = (const float4*)(embed + (size_t)warp * CH);
            float4 v0 = row[lane * 2], v1 = row[lane * 2 + 1];
            float s = v0.x*v0.x + v0.y*v0.y + v0.z*v0.z + v0.w*v0.w
                    + v1.x*v1.x + v1.y*v1.y + v1.z*v1.z + v1.w*v1.w;
            #pragma unroll
            for (int o = 16; o; o >>= 1) s += __shfl_xor_sync(0xffffffffu, s, o);
            if (lane == 0) g_e2[warp] = s;
            __nv_bfloat16 h[8] = {
                __float2bfloat16(v0.x), __float2bfloat16(v0.y),
                __float2bfloat16(v0.z), __float2bfloat16(v0.w),
                __float2bfloat16(v1.x), __float2bfloat16(v1.y),
                __float2bfloat16(v1.z), __float2bfloat16(v1.w) };
            *(uint4*)(g_Eh + (size_t)warp * CH + lane * 8) = *(const uint4*)h;
        }
        if (gid < KCODE) g_counts[gid] = 0;
        if (gid < 1024)  g_partials[gid] = 0.0;
        if (gid == 0)    { g_nflag = 0; g_done = 0; }
        return;
    }
    __shared__ float T[32][33];
    int tx = threadIdx.x, ty = threadIdx.y;          // block (32,8)
    int m0 = blockIdx.x * 32, c0 = blockIdx.y * 32, b = blockIdx.z;
    #pragma unroll
    for (int i = 0; i < 4; i++) {
        int c = ty + i * 8;
        T[c][tx] = z_e[((size_t)b * CH + c0 + c) * HWS + m0 + tx];   // coalesced in m
    }
    __syncthreads();
    #pragma unroll
    for (int i = 0; i < 4; i++) {
        int r = ty + i * 8;                                           // m_local
        float v = T[tx][r];                                           // tx = c_local
        size_t o = (size_t)(b * HWS + m0 + r) * CH + c0 + tx;         // coalesced in c
        g_Zh[o] = __float2bfloat16(v);
        g_Zf[o] = v;
    }
}

// ───────────── kernel 2: HMMA GEMM (K=256) + argmin + margin flagging ──────────
// Writes ONLY g_best[pos] + near-tie flags. Flagged positions get the ~0ull
// sentinel so repair's fp32-exact keys fully decide them.
__global__ void __launch_bounds__(256, 1) mma_argmin_kernel() {
    extern __shared__ char smem[];
    const uint32_t sb = smem_u32(smem);
    const int tid = threadIdx.x;
    const int lane = tid & 31, wid = tid >> 5;
    const int mrow = wid * 32;
    const int n0 = blockIdx.x * 256;

    // A resident: 256 rows x 32 x 16B, coalesced
    #pragma unroll
    for (int it = 0; it < 32; it++) {
        int u = tid + it * 256;
        int row = u >> 5, cu = u & 31;
        cp16(sb + SB_A + row * 512 + ((cu * 16) ^ ((row & 7) << 4)),
             g_Zh + (size_t)(n0 + row) * 256 + cu * 8);
    }
    CP_COMMIT();
    // B chunk 0 into buf0
    #pragma unroll
    for (int it = 0; it < 8; it++) {
        int u = tid + it * 256;
        int row = u >> 5, cu = u & 31;
        cp16(sb + SB_B0 + row * 512 + ((cu * 16) ^ ((row & 7) << 4)),
             g_Eh + (size_t)row * 256 + cu * 8);
    }
    CP_COMMIT();

    unsigned long long bs[4], ss[4];
    #pragma unroll
    for (int si = 0; si < 4; si++) { bs[si] = ~0ull; ss[si] = ~0ull; }

    float acc[2][8][4];
    const uint32_t bbuf[2] = { sb + SB_B0, sb + SB_B1 };

    for (int chunk = 0; chunk < 16; chunk++) {
        CP_WAIT0();                // B[chunk] landed (chunk 0: also A)
        __syncthreads();           // all warps past compute of chunk-1
        if (chunk < 15) {          // prefetch next B into the other buffer
            #pragma unroll
            for (int it = 0; it < 8; it++) {
                int u = tid + it * 256;
                int row = u >> 5, cu = u & 31;
                cp16(bbuf[(chunk + 1) & 1] + row * 512 + ((cu * 16) ^ ((row & 7) << 4)),
                     g_Eh + (size_t)((chunk + 1) * 64 + row) * 256 + cu * 8);
            }
            CP_COMMIT();
        }

        const uint32_t bB = bbuf[chunk & 1];
        #pragma unroll
        for (int mt = 0; mt < 2; mt++)
            #pragma unroll
            for (int nt = 0; nt < 8; nt++)
                #pragma unroll
                for (int e = 0; e < 4; e++) acc[mt][nt][e] = 0.f;

        #pragma unroll
        for (int ks = 0; ks < 16; ks++) {
            uint32_t a[2][4];
            #pragma unroll
            for (int mt = 0; mt < 2; mt++) {
                int row = mrow + mt * 16 + (lane & 15);
                int colb = ks * 32 + ((lane >> 4) << 4);
                ldsm_x4(a[mt][0], a[mt][1], a[mt][2], a[mt][3],
                        sb + SB_A + row * 512 + (colb ^ ((row & 7) << 4)));
            }
            uint32_t bq[4][4];
            #pragma unroll
            for (int p = 0; p < 4; p++) {
                int row = p * 16 + (lane & 7) + ((lane >> 4) << 3);
                int colb = ks * 32 + ((lane & 8) << 1);
                ldsm_x4(bq[p][0], bq[p][1], bq[p][2], bq[p][3],
                        bB + row * 512 + (colb ^ ((row & 7) << 4)));
            }
            #pragma unroll
            for (int mt = 0; mt < 2; mt++)
                #pragma unroll
                for (int nt = 0; nt < 8; nt++)
                    mma16816(acc[mt][nt], a[mt], bq[nt >> 1][(nt & 1) * 2],
                             bq[nt >> 1][(nt & 1) * 2 + 1]);
        }

        // epilogue: dist = e2 - 2S; track best & second-best
        const int cb = chunk * 64;
        #pragma unroll
        for (int mt = 0; mt < 2; mt++)
            #pragma unroll
            for (int nt = 0; nt < 8; nt++)
                #pragma unroll
                for (int e = 0; e < 4; e++) {
                    int code = cb + nt * 8 + (lane & 3) * 2 + (e & 1);
                    float dist = __ldg(&g_e2[code]) - 2.0f * acc[mt][nt][e];
                    unsigned long long cand =
                        ((unsigned long long)ordmap(dist) << 32) | (unsigned)code;
                    int si = mt * 2 + (e >> 1);
                    if (cand < bs[si]) { ss[si] = bs[si]; bs[si] = cand; }
                    else if (cand < ss[si]) ss[si] = cand;
                }
    }

    // quad merge (lanes sharing a row) + writeout
    #pragma unroll
    for (int si = 0; si < 4; si++) {
        unsigned long long b = bs[si], s = ss[si];
        #pragma unroll
        for (int m = 1; m <= 2; m <<= 1) {
            unsigned long long ob = __shfl_xor_sync(0xffffffffu, b, m);
            unsigned long long os = __shfl_xor_sync(0xffffffffu, s, m);
            unsigned long long nb = b < ob ? b : ob;
            unsigned long long mx = b < ob ? ob : b;
            unsigned long long ms = s < os ? s : os;
            b = nb; s = mx < ms ? mx : ms;
        }
        if ((lane & 3) == 0) {
            int row = mrow + (si >> 1) * 16 + (lane >> 2) + (si & 1) * 8;
            int pos = n0 + row;
            float fb = unord((unsigned)(b >> 32));
            float fs = unord((unsigned)(s >> 32));
            if (fs - fb < MARGIN) {
                g_best[pos] = ~0ull;               // sentinel: fp32 keys only
                int sl = atomicAdd(&g_nflag, 1);
                g_flag[sl] = pos;
            } else {
                g_best[pos] = b;                   // safe: code proven by margin
            }
        }
    }
}

// ───────────── kernel 3: exact fp32 repair (dual chains per code) ──────────────
// Block = (32 flagged positions) x (64-code chunk); lane = position.
// Per C-chunk of 64: x chunk -> 16 float4 registers once; warp's 8 codes via
// warp-uniform broadcast LDS. TWO accumulation chains per code (even/odd q)
// halve the FFMA dependency depth -> latency fully hidden at 4 warps/SMSP.
__global__ void __launch_bounds__(256) repair_kernel(const float* __restrict__ embed) {
    extern __shared__ __align__(16) float dyn[];
    float* Es = dyn;                               // [64][256] (uniform reads)
    float* Xs = dyn + RP_ES;                       // [32][260] (padded rows)
    unsigned long long* sbest = (unsigned long long*)(dyn + RP_ES + RP_XS);
    const int tid = threadIdx.x;
    const int lane = tid & 31, wrp = tid >> 5;     // lane = position slot
    const int nf = g_nflag;
    const int nw = ((nf + 31) >> 5) * 16;

    for (int w = blockIdx.x; w < nw; w += gridDim.x) {
        const int pg = w >> 4, chunk = w & 15;
        const int base = pg * 32;
        const int cnt = min(32, nf - base);

        // stage 64 embed rows (64KB), coalesced float4
        for (int i = tid; i < 64 * 64; i += 256) {
            int r = i >> 6, c4 = i & 63;
            *(float4*)&Es[r * 256 + c4 * 4] =
                __ldg((const float4*)(embed + (size_t)(chunk * 64 + r) * CH) + c4);
        }
        // stage 32 x-vectors from g_Zf, coalesced float4
        for (int i = tid; i < 32 * 64; i += 256) {
            int p = i >> 6, c4 = i & 63;
            int pos = g_flag[base + (p < cnt ? p : 0)];
            *(float4*)&Xs[p * 260 + c4 * 4] =
                __ldg((const float4*)(g_Zf + (size_t)pos * CH) + c4);
        }
        if (tid < 32) sbest[tid] = ~0ull;
        __syncthreads();

        float acc0[8], acc1[8];
        #pragma unroll
        for (int j = 0; j < 8; j++) { acc0[j] = 0.f; acc1[j] = 0.f; }

        #pragma unroll 1
        for (int cc = 0; cc < 4; cc++) {           // C-chunks of 64
            float4 xv[16];
            const float4* xr = (const float4*)(Xs + lane * 260 + cc * 64);
            #pragma unroll
            for (int q = 0; q < 16; q++) xv[q] = xr[q];   // x chunk -> registers

            #pragma unroll 1
            for (int j = 0; j < 8; j++) {          // warp's 8 codes, serial
                const float4* er =                  // warp-uniform address
                    (const float4*)(Es + (wrp * 8 + j) * 256 + cc * 64);
                float a0 = acc0[j], a1 = acc1[j];
                #pragma unroll
                for (int q = 0; q < 16; q += 2) {  // two independent chains
                    float4 e0 = er[q], e1 = er[q + 1];     // broadcast LDS.128
                    a0 = fmaf(e0.x, xv[q].x, a0); a0 = fmaf(e0.y, xv[q].y, a0);
                    a0 = fmaf(e0.z, xv[q].z, a0); a0 = fmaf(e0.w, xv[q].w, a0);
                    a1 = fmaf(e1.x, xv[q + 1].x, a1); a1 = fmaf(e1.y, xv[q + 1].y, a1);
                    a1 = fmaf(e1.z, xv[q + 1].z, a1); a1 = fmaf(e1.w, xv[q + 1].w, a1);
                }
                acc0[j] = a0; acc1[j] = a1;
            }
        }

        unsigned long long best = ~0ull;
        #pragma unroll
        for (int j = 0; j < 8; j++) {
            int k = chunk * 64 + wrp * 8 + j;
            float d = __ldg(&g_e2[k]) - 2.f * (acc0[j] + acc1[j]);
            unsigned long long cand =
                ((unsigned long long)ordmap(d) << 32) | (unsigned)k;
            if (cand < best) best = cand;          // ties -> lower k (packed)
        }
        atomicMin(&sbest[lane], best);             // 8 warps merge per position
        __syncthreads();
        if (tid < cnt) atomicMin(&g_best[g_flag[base + tid]], sbest[tid]);
        __syncthreads();                           // protect Es/Xs/sbest reuse
    }
}

// ───────────── kernel 4: z_q + loss + indices + counts + scalars (fused) ───────
// Thread = (b, m-quad, c-segment of 16): g_best read ONCE per thread; grid
// 512 blocks (2x round-14 parallelism). Last finishing block reduces
// partials + counts (deterministic fixed-order).
__global__ void __launch_bounds__(256) zq_kernel(
    const float* __restrict__ z_e, const float* __restrict__ embed,
    float* __restrict__ out) {
    __shared__ double sred[256];
    __shared__ int s_ticket;
    const int tid = threadIdx.x;                    // mq (m-quad index)
    const int b = blockIdx.x >> 4;                  // blockIdx = b*16 + cseg
    const int cseg = blockIdx.x & 15;               // 16 channels per segment
    const int pbase = (b << 10) + tid * 4;

    ulonglong2 b01 = *(const ulonglong2*)&g_best[pbase];
    ulonglong2 b23 = *(const ulonglong2*)&g_best[pbase + 2];
    const int i0 = (int)(unsigned)(b01.x), i1 = (int)(unsigned)(b01.y);
    const int i2 = (int)(unsigned)(b23.x), i3 = (int)(unsigned)(b23.y);

    if (cseg == 0) {                                // once per position
        out[TOT + pbase + 0] = (float)i0;
        out[TOT + pbase + 1] = (float)i1;
        out[TOT + pbase + 2] = (float)i2;
        out[TOT + pbase + 3] = (float)i3;
        atomicAdd(&g_counts[i0], 1);
        atomicAdd(&g_counts[i1], 1);
        atomicAdd(&g_counts[i2], 1);
        atomicAdd(&g_counts[i3], 1);
    }

    const float4* e0 = (const float4*)(embed + (size_t)i0 * CH);
    const float4* e1 = (const float4*)(embed + (size_t)i1 * CH);
    const float4* e2 = (const float4*)(embed + (size_t)i2 * CH);
    const float4* e3 = (const float4*)(embed + (size_t)i3 * CH);

    float loc = 0.f;
    #pragma unroll
    for (int cq = 0; cq < 4; cq++) {
        const int c = (cseg << 4) + cq * 4;         // channels c..c+3
        float4 q0 = __ldg(e0 + (c >> 2));
        float4 q1 = __ldg(e1 + (c >> 2));
        float4 q2 = __ldg(e2 + (c >> 2));
        float4 q3 = __ldg(e3 + (c >> 2));
        #pragma unroll
        for (int j = 0; j < 4; j++) {
            size_t e = ((size_t)(b * CH + c + j) << 10) + tid * 4;
            float4 z = *(const float4*)&z_e[e];
            float4 qv = make_float4(f4_elem(q0, j), f4_elem(q1, j),
                                    f4_elem(q2, j), f4_elem(q3, j));
            *(float4*)&out[e] = qv;
            float dx = z.x - qv.x, dy = z.y - qv.y;
            float dz = z.z - qv.z, dw = z.w - qv.w;
            loc = fmaf(dx, dx, loc); loc = fmaf(dy, dy, loc);
            loc = fmaf(dz, dz, loc); loc = fmaf(dw, dw, loc);
        }
    }

    sred[tid] = (double)loc;
    __syncthreads();
    for (int o = 128; o; o >>= 1) {
        if (tid < o) sred[tid] += sred[tid + o];
        __syncthreads();
    }
    if (tid == 0) {
        g_partials[blockIdx.x] = sred[0];
        __threadfence();
        s_ticket = atomicAdd(&g_done, 1) + 1;
    }
    __syncthreads();
    if (s_ticket == (int)gridDim.x) {               // last block: scalars
        __threadfence();                             // see all partials/counts
        double ls = 0.0, es = 0.0;
        for (int i = tid; i < 1024; i += 256) {      // fixed order per thread
            if (i < 512) ls += g_partials[i];        // 512 partials used
            float p = (float)g_counts[i] / (float)NPOS;
            es += (double)(p * logf(p + 1e-10f));
        }
        sred[tid] = ls;
        __syncthreads();
        for (int o = 128; o; o >>= 1) {
            if (tid < o) sred[tid] += sred[tid + o];
            __syncthreads();
        }
        double lsum = sred[0];
        __syncthreads();
        sred[tid] = es;
        __syncthreads();
        for (int o = 128; o; o >>= 1) {
            if (tid < o) sred[tid] += sred[tid + o];
            __syncthreads();
        }
        if (tid == 0) {
            out[TOT + NPOS]     = BETA_W * (float)(lsum / (double)TOT);
            out[TOT + NPOS + 1] = expf(-(float)sred[0]);
        }
    }
}

// ───────────────────────── host ─────────────────────────
extern "C" void kernel_launch(void* const* d_in, const int* in_sizes, int n_in,
                              void* d_out, int out_size) {
    const float* z_e   = (const float*)d_in[0];   // (32,256,32,32) f32
    const float* embed = (const float*)d_in[1];   // (1024,256)     f32
    float* out = (float*)d_out;

    cudaFuncSetAttribute(mma_argmin_kernel,
                         cudaFuncAttributeMaxDynamicSharedMemorySize, SMEM_TOTAL);
    cudaFuncSetAttribute(repair_kernel,
                         cudaFuncAttributeMaxDynamicSharedMemorySize, RP_SMEM);

    convert_init_kernel<<<dim3(HWS / 32, CH / 32, BATCH + 1), dim3(32, 8)>>>(z_e, embed);
    mma_argmin_kernel<<<NPOS / 256, 256, SMEM_TOTAL>>>();
    repair_kernel<<<1024, 256, RP_SMEM>>>(embed);
    zq_kernel<<<BATCH * 16, 256>>>(z_e, embed, out);
}

// round 16
// speedup vs baseline: 1.1175x; 1.1175x over previous
#include <cuda_runtime.h>
#include <cuda_bf16.h>
#include <cstdint>

// ───────────────────────── problem constants ─────────────────────────
constexpr int BATCH = 32;
constexpr int CH    = 256;     // C == D == K(gemm)
constexpr int KCODE = 1024;    // codebook size
constexpr int HWS   = 1024;    // H*W
constexpr int NPOS  = BATCH * HWS;                 // 32768 positions
constexpr long long TOT = (long long)NPOS * CH;    // 8388608 z_e elements
constexpr float BETA_W = 0.25f;
// bf16 single-product distance error margin; everything inside is re-decided
// EXACTLY in fp32 by repair. Flagged positions get a ~0ull sentinel in g_best
// so ONLY fp32-exact keys compete there.
constexpr float MARGIN = 0.75f;

typedef unsigned long long ull;

// smem layout for MMA kernel (bytes)
constexpr int SB_A  = 0;                  // A: 256 rows x 512B swizzled = 131072
constexpr int SB_B0 = 131072;             // B buf0: 64 rows x 512B      = 32768
constexpr int SB_B1 = 163840;             // B buf1                      = 32768
constexpr int SMEM_TOTAL = 196608;        // 192KB

// repair kernel smem (round-10/14 measured optimum — FROZEN):
// Es[64][256] + Xs[32][260] floats + sbest[32] u64
constexpr int RP_ES   = 64 * 256;                       // floats (uniform access)
constexpr int RP_XS   = 32 * 260;                       // floats (padded rows)
constexpr int RP_SMEM = (RP_ES + RP_XS) * 4 + 32 * 8;   // 99072 bytes

// ───────────────────────── device scratch ─────────────────────────
__device__ __align__(16) __nv_bfloat16 g_Zh[(size_t)NPOS * CH];  // [n][c] bf16
__device__ __align__(16) float         g_Zf[(size_t)NPOS * CH];  // [n][c] fp32
__device__ __align__(16) __nv_bfloat16 g_Eh[(size_t)KCODE * CH]; // [k][c] bf16
__device__ float  g_e2[KCODE];
__device__ int    g_counts[KCODE];
__device__ double g_partials[1024];
__device__ int    g_nflag;
__device__ int    g_done;
__device__ int    g_flag[NPOS];
__device__ unsigned long long g_best[NPOS];   // packed (ordmap(dist)<<32)|code

// ───────────────────────── PTX helpers ─────────────────────────
__device__ __forceinline__ uint32_t smem_u32(const void* p) {
    uint32_t a;
    asm("{ .reg .u64 t; cvta.to.shared.u64 t, %1; cvt.u32.u64 %0, t; }" : "=r"(a) : "l"(p));
    return a;
}
__device__ __forceinline__ void cp16(uint32_t dst, const void* src) {
    asm volatile("cp.async.cg.shared.global [%0], [%1], 16;" :: "r"(dst), "l"(src));
}
#define CP_COMMIT() asm volatile("cp.async.commit_group;" ::: "memory")
#define CP_WAIT0()  asm volatile("cp.async.wait_group 0;" ::: "memory")

__device__ __forceinline__ void ldsm_x4(uint32_t& r0, uint32_t& r1, uint32_t& r2,
                                        uint32_t& r3, uint32_t addr) {
    asm volatile("ldmatrix.sync.aligned.m8n8.x4.shared.b16 {%0,%1,%2,%3}, [%4];"
                 : "=r"(r0), "=r"(r1), "=r"(r2), "=r"(r3) : "r"(addr));
}
__device__ __forceinline__ void mma16816(float* d, const uint32_t* a, uint32_t b0, uint32_t b1) {
    asm volatile("mma.sync.aligned.m16n8k16.row.col.f32.bf16.bf16.f32 "
                 "{%0,%1,%2,%3}, {%4,%5,%6,%7}, {%8,%9}, {%0,%1,%2,%3};"
                 : "+f"(d[0]), "+f"(d[1]), "+f"(d[2]), "+f"(d[3])
                 : "r"(a[0]), "r"(a[1]), "r"(a[2]), "r"(a[3]), "r"(b0), "r"(b1));
}
__device__ __forceinline__ unsigned ordmap(float f) {
    unsigned u = __float_as_uint(f);
    return (u & 0x80000000u) ? ~u : (u | 0x80000000u);
}
__device__ __forceinline__ float unord(unsigned v) {
    v = (v & 0x80000000u) ? (v & 0x7FFFFFFFu) : ~v;
    return __uint_as_float(v);
}
__device__ __forceinline__ float f4_elem(const float4& v, int j) {
    switch (j) { case 0: return v.x; case 1: return v.y; case 2: return v.z; }
    return v.w;
}

// ───────────── kernel 1: transpose z_e + (fused) init plane ─────────────
// grid (32, 8, 33): z<32 = transpose planes; z==32 = init work.
__global__ void convert_init_kernel(const float* __restrict__ z_e,
                                    const float* __restrict__ embed) {
    if (blockIdx.z == BATCH) {
        int bid = blockIdx.y * gridDim.x + blockIdx.x;          // 0..255
        int tid = threadIdx.y * 32 + threadIdx.x;
        int gid = bid * 256 + tid;                              // 0..65535
        int warp = gid >> 5, lane = gid & 31;
        if (warp < KCODE) {
            const float4* row = (const float4*)(embed + (size_t)warp * CH);
            float4 v0 = row[lane * 2], v1 = row[lane * 2 + 1];
            float s = v0.x*v0.x + v0.y*v0.y + v0.z*v0.z + v0.w*v0.w
                    + v1.x*v1.x + v1.y*v1.y + v1.z*v1.z + v1.w*v1.w;
            #pragma unroll
            for (int o = 16; o; o >>= 1) s += __shfl_xor_sync(0xffffffffu, s, o);
            if (lane == 0) g_e2[warp] = s;
            __nv_bfloat16 h[8] = {
                __float2bfloat16(v0.x), __float2bfloat16(v0.y),
                __float2bfloat16(v0.z), __float2bfloat16(v0.w),
                __float2bfloat16(v1.x), __float2bfloat16(v1.y),
                __float2bfloat16(v1.z), __float2bfloat16(v1.w) };
            *(uint4*)(g_Eh + (size_t)warp * CH + lane * 8) = *(const uint4*)h;
        }
        if (gid < KCODE) g_counts[gid] = 0;
        if (gid < 1024)  g_partials[gid] = 0.0;
        if (gid == 0)    { g_nflag = 0; g_done = 0; }
        return;
    }
    __shared__ float T[32][33];
    int tx = threadIdx.x, ty = threadIdx.y;          // block (32,8)
    int m0 = blockIdx.x * 32, c0 = blockIdx.y * 32, b = blockIdx.z;
    #pragma unroll
    for (int i = 0; i < 4; i++) {
        int c = ty + i * 8;
        T[c][tx] = z_e[((size_t)b * CH + c0 + c) * HWS + m0 + tx];   // coalesced in m
    }
    __syncthreads();
    #pragma unroll
    for (int i = 0; i < 4; i++) {
        int r = ty + i * 8;                                           // m_local
        float v = T[tx][r];                                           // tx = c_local
        size_t o = (size_t)(b * HWS + m0 + r) * CH + c0 + tx;         // coalesced in c
        g_Zh[o] = __float2bfloat16(v);
        g_Zf[o] = v;
    }
}

// ───────────── kernel 2: HMMA GEMM (K=256) + argmin + margin flagging ──────────
// Writes ONLY g_best[pos] + near-tie flags. Flagged positions get the ~0ull
// sentinel so repair's fp32-exact keys fully decide them.
__global__ void __launch_bounds__(256, 1) mma_argmin_kernel() {
    extern __shared__ char smem[];
    const uint32_t sb = smem_u32(smem);
    const int tid = threadIdx.x;
    const int lane = tid & 31, wid = tid >> 5;
    const int mrow = wid * 32;
    const int n0 = blockIdx.x * 256;

    // A resident: 256 rows x 32 x 16B, coalesced
    #pragma unroll
    for (int it = 0; it < 32; it++) {
        int u = tid + it * 256;
        int row = u >> 5, cu = u & 31;
        cp16(sb + SB_A + row * 512 + ((cu * 16) ^ ((row & 7) << 4)),
             g_Zh + (size_t)(n0 + row) * 256 + cu * 8);
    }
    CP_COMMIT();
    // B chunk 0 into buf0
    #pragma unroll
    for (int it = 0; it < 8; it++) {
        int u = tid + it * 256;
        int row = u >> 5, cu = u & 31;
        cp16(sb + SB_B0 + row * 512 + ((cu * 16) ^ ((row & 7) << 4)),
             g_Eh + (size_t)row * 256 + cu * 8);
    }
    CP_COMMIT();

    unsigned long long bs[4], ss[4];
    #pragma unroll
    for (int si = 0; si < 4; si++) { bs[si] = ~0ull; ss[si] = ~0ull; }

    float acc[2][8][4];
    const uint32_t bbuf[2] = { sb + SB_B0, sb + SB_B1 };

    for (int chunk = 0; chunk < 16; chunk++) {
        CP_WAIT0();                // B[chunk] landed (chunk 0: also A)
        __syncthreads();           // all warps past compute of chunk-1
        if (chunk < 15) {          // prefetch next B into the other buffer
            #pragma unroll
            for (int it = 0; it < 8; it++) {
                int u = tid + it * 256;
                int row = u >> 5, cu = u & 31;
                cp16(bbuf[(chunk + 1) & 1] + row * 512 + ((cu * 16) ^ ((row & 7) << 4)),
                     g_Eh + (size_t)((chunk + 1) * 64 + row) * 256 + cu * 8);
            }
            CP_COMMIT();
        }

        const uint32_t bB = bbuf[chunk & 1];
        #pragma unroll
        for (int mt = 0; mt < 2; mt++)
            #pragma unroll
            for (int nt = 0; nt < 8; nt++)
                #pragma unroll
                for (int e = 0; e < 4; e++) acc[mt][nt][e] = 0.f;

        #pragma unroll
        for (int ks = 0; ks < 16; ks++) {
            uint32_t a[2][4];
            #pragma unroll
            for (int mt = 0; mt < 2; mt++) {
                int row = mrow + mt * 16 + (lane & 15);
                int colb = ks * 32 + ((lane >> 4) << 4);
                ldsm_x4(a[mt][0], a[mt][1], a[mt][2], a[mt][3],
                        sb + SB_A + row * 512 + (colb ^ ((row & 7) << 4)));
            }
            uint32_t bq[4][4];
            #pragma unroll
            for (int p = 0; p < 4; p++) {
                int row = p * 16 + (lane & 7) + ((lane >> 4) << 3);
                int colb = ks * 32 + ((lane & 8) << 1);
                ldsm_x4(bq[p][0], bq[p][1], bq[p][2], bq[p][3],
                        bB + row * 512 + (colb ^ ((row & 7) << 4)));
            }
            #pragma unroll
            for (int mt = 0; mt < 2; mt++)
                #pragma unroll
                for (int nt = 0; nt < 8; nt++)
                    mma16816(acc[mt][nt], a[mt], bq[nt >> 1][(nt & 1) * 2],
                             bq[nt >> 1][(nt & 1) * 2 + 1]);
        }

        // epilogue: dist = e2 - 2S; track best & second-best
        const int cb = chunk * 64;
        #pragma unroll
        for (int mt = 0; mt < 2; mt++)
            #pragma unroll
            for (int nt = 0; nt < 8; nt++)
                #pragma unroll
                for (int e = 0; e < 4; e++) {
                    int code = cb + nt * 8 + (lane & 3) * 2 + (e & 1);
                    float dist = __ldg(&g_e2[code]) - 2.0f * acc[mt][nt][e];
                    unsigned long long cand =
                        ((unsigned long long)ordmap(dist) << 32) | (unsigned)code;
                    int si = mt * 2 + (e >> 1);
                    if (cand < bs[si]) { ss[si] = bs[si]; bs[si] = cand; }
                    else if (cand < ss[si]) ss[si] = cand;
                }
    }

    // quad merge (lanes sharing a row) + writeout
    #pragma unroll
    for (int si = 0; si < 4; si++) {
        unsigned long long b = bs[si], s = ss[si];
        #pragma unroll
        for (int m = 1; m <= 2; m <<= 1) {
            unsigned long long ob = __shfl_xor_sync(0xffffffffu, b, m);
            unsigned long long os = __shfl_xor_sync(0xffffffffu, s, m);
            unsigned long long nb = b < ob ? b : ob;
            unsigned long long mx = b < ob ? ob : b;
            unsigned long long ms = s < os ? s : os;
            b = nb; s = mx < ms ? mx : ms;
        }
        if ((lane & 3) == 0) {
            int row = mrow + (si >> 1) * 16 + (lane >> 2) + (si & 1) * 8;
            int pos = n0 + row;
            float fb = unord((unsigned)(b >> 32));
            float fs = unord((unsigned)(s >> 32));
            if (fs - fb < MARGIN) {
                g_best[pos] = ~0ull;               // sentinel: fp32 keys only
                int sl = atomicAdd(&g_nflag, 1);
                g_flag[sl] = pos;
            } else {
                g_best[pos] = b;                   // safe: code proven by margin
            }
        }
    }
}

// ───────────── kernel 3: exact fp32 repair (round-10/14 FROZEN optimum) ────────
// Block = (32 flagged positions) x (64-code chunk); lane = position.
// Per C-chunk of 64: x chunk -> 16 float4 registers once, then warp's 8 codes
// via warp-uniform broadcast LDS into 8 persistent accumulators. Single chain
// per code — dual chains (round 15) crossed the 2-blocks/SM register cliff.
__global__ void __launch_bounds__(256) repair_kernel(const float* __restrict__ embed) {
    extern __shared__ __align__(16) float dyn[];
    float* Es = dyn;                               // [64][256] (uniform reads)
    float* Xs = dyn + RP_ES;                       // [32][260] (padded rows)
    unsigned long long* sbest = (unsigned long long*)(dyn + RP_ES + RP_XS);
    const int tid = threadIdx.x;
    const int lane = tid & 31, wrp = tid >> 5;     // lane = position slot
    const int nf = g_nflag;
    const int nw = ((nf + 31) >> 5) * 16;

    for (int w = blockIdx.x; w < nw; w += gridDim.x) {
        const int pg = w >> 4, chunk = w & 15;
        const int base = pg * 32;
        const int cnt = min(32, nf - base);

        // stage 64 embed rows (64KB), coalesced float4
        for (int i = tid; i < 64 * 64; i += 256) {
            int r = i >> 6, c4 = i & 63;
            *(float4*)&Es[r * 256 + c4 * 4] =
                __ldg((const float4*)(embed + (size_t)(chunk * 64 + r) * CH) + c4);
        }
        // stage 32 x-vectors from g_Zf, coalesced float4
        for (int i = tid; i < 32 * 64; i += 256) {
            int p = i >> 6, c4 = i & 63;
            int pos = g_flag[base + (p < cnt ? p : 0)];
            *(float4*)&Xs[p * 260 + c4 * 4] =
                __ldg((const float4*)(g_Zf + (size_t)pos * CH) + c4);
        }
        if (tid < 32) sbest[tid] = ~0ull;
        __syncthreads();

        float acc[8];
        #pragma unroll
        for (int j = 0; j < 8; j++) acc[j] = 0.f;

        #pragma unroll 1
        for (int cc = 0; cc < 4; cc++) {           // C-chunks of 64
            float4 xv[16];
            const float4* xr = (const float4*)(Xs + lane * 260 + cc * 64);
            #pragma unroll
            for (int q = 0; q < 16; q++) xv[q] = xr[q];   // x chunk -> registers

            #pragma unroll 1
            for (int j = 0; j < 8; j++) {          // warp's 8 codes, serial
                const float4* er =                  // warp-uniform address
                    (const float4*)(Es + (wrp * 8 + j) * 256 + cc * 64);
                float a = acc[j];
                #pragma unroll
                for (int q = 0; q < 16; q++) {
                    float4 e = er[q];              // broadcast LDS.128
                    a = fmaf(e.x, xv[q].x, a); a = fmaf(e.y, xv[q].y, a);
                    a = fmaf(e.z, xv[q].z, a); a = fmaf(e.w, xv[q].w, a);
                }
                acc[j] = a;
            }
        }

        unsigned long long best = ~0ull;
        #pragma unroll
        for (int j = 0; j < 8; j++) {
            int k = chunk * 64 + wrp * 8 + j;
            float d = __ldg(&g_e2[k]) - 2.f * acc[j];
            unsigned long long cand =
                ((unsigned long long)ordmap(d) << 32) | (unsigned)k;
            if (cand < best) best = cand;          // ties -> lower k (packed)
        }
        atomicMin(&sbest[lane], best);             // 8 warps merge per position
        __syncthreads();
        if (tid < cnt) atomicMin(&g_best[g_flag[base + tid]], sbest[tid]);
        __syncthreads();                           // protect Es/Xs/sbest reuse
    }
}

// ───────────── kernel 4: z_q + loss + indices + counts + scalars (fused) ───────
// Thread = (b, m-quad, c-segment of 16): g_best read ONCE per thread; grid
// 512 blocks. Last finishing block reduces partials + counts (fixed order).
__global__ void __launch_bounds__(256) zq_kernel(
    const float* __restrict__ z_e, const float* __restrict__ embed,
    float* __restrict__ out) {
    __shared__ double sred[256];
    __shared__ int s_ticket;
    const int tid = threadIdx.x;                    // mq (m-quad index)
    const int b = blockIdx.x >> 4;                  // blockIdx = b*16 + cseg
    const int cseg = blockIdx.x & 15;               // 16 channels per segment
    const int pbase = (b << 10) + tid * 4;

    ulonglong2 b01 = *(const ulonglong2*)&g_best[pbase];
    ulonglong2 b23 = *(const ulonglong2*)&g_best[pbase + 2];
    const int i0 = (int)(unsigned)(b01.x), i1 = (int)(unsigned)(b01.y);
    const int i2 = (int)(unsigned)(b23.x), i3 = (int)(unsigned)(b23.y);

    if (cseg == 0) {                                // once per position
        out[TOT + pbase + 0] = (float)i0;
        out[TOT + pbase + 1] = (float)i1;
        out[TOT + pbase + 2] = (float)i2;
        out[TOT + pbase + 3] = (float)i3;
        atomicAdd(&g_counts[i0], 1);
        atomicAdd(&g_counts[i1], 1);
        atomicAdd(&g_counts[i2], 1);
        atomicAdd(&g_counts[i3], 1);
    }

    const float4* e0 = (const float4*)(embed + (size_t)i0 * CH);
    const float4* e1 = (const float4*)(embed + (size_t)i1 * CH);
    const float4* e2 = (const float4*)(embed + (size_t)i2 * CH);
    const float4* e3 = (const float4*)(embed + (size_t)i3 * CH);

    float loc = 0.f;
    #pragma unroll
    for (int cq = 0; cq < 4; cq++) {
        const int c = (cseg << 4) + cq * 4;         // channels c..c+3
        float4 q0 = __ldg(e0 + (c >> 2));
        float4 q1 = __ldg(e1 + (c >> 2));
        float4 q2 = __ldg(e2 + (c >> 2));
        float4 q3 = __ldg(e3 + (c >> 2));
        #pragma unroll
        for (int j = 0; j < 4; j++) {
            size_t e = ((size_t)(b * CH + c + j) << 10) + tid * 4;
            float4 z = *(const float4*)&z_e[e];
            float4 qv = make_float4(f4_elem(q0, j), f4_elem(q1, j),
                                    f4_elem(q2, j), f4_elem(q3, j));
            *(float4*)&out[e] = qv;
            float dx = z.x - qv.x, dy = z.y - qv.y;
            float dz = z.z - qv.z, dw = z.w - qv.w;
            loc = fmaf(dx, dx, loc); loc = fmaf(dy, dy, loc);
            loc = fmaf(dz, dz, loc); loc = fmaf(dw, dw, loc);
        }
    }

    sred[tid] = (double)loc;
    __syncthreads();
    for (int o = 128; o; o >>= 1) {
        if (tid < o) sred[tid] += sred[tid + o];
        __syncthreads();
    }
    if (tid == 0) {
        g_partials[blockIdx.x] = sred[0];
        __threadfence();
        s_ticket = atomicAdd(&g_done, 1) + 1;
    }
    __syncthreads();
    if (s_ticket == (int)gridDim.x) {               // last block: scalars
        __threadfence();                             // see all partials/counts
        double ls = 0.0, es = 0.0;
        for (int i = tid; i < 1024; i += 256) {      // fixed order per thread
            if (i < 512) ls += g_partials[i];        // 512 partials used
            float p = (float)g_counts[i] / (float)NPOS;
            es += (double)(p * logf(p + 1e-10f));
        }
        sred[tid] = ls;
        __syncthreads();
        for (int o = 128; o; o >>= 1) {
            if (tid < o) sred[tid] += sred[tid + o];
            __syncthreads();
        }
        double lsum = sred[0];
        __syncthreads();
        sred[tid] = es;
        __syncthreads();
        for (int o = 128; o; o >>= 1) {
            if (tid < o) sred[tid] += sred[tid + o];
            __syncthreads();
        }
        if (tid == 0) {
            out[TOT + NPOS]     = BETA_W * (float)(lsum / (double)TOT);
            out[TOT + NPOS + 1] = expf(-(float)sred[0]);
        }
    }
}

// ───────────────────────── host ─────────────────────────
extern "C" void kernel_launch(void* const* d_in, const int* in_sizes, int n_in,
                              void* d_out, int out_size) {
    const float* z_e   = (const float*)d_in[0];   // (32,256,32,32) f32
    const float* embed = (const float*)d_in[1];   // (1024,256)     f32
    float* out = (float*)d_out;

    cudaFuncSetAttribute(mma_argmin_kernel,
                         cudaFuncAttributeMaxDynamicSharedMemorySize, SMEM_TOTAL);
    cudaFuncSetAttribute(repair_kernel,
                         cudaFuncAttributeMaxDynamicSharedMemorySize, RP_SMEM);

    convert_init_kernel<<<dim3(HWS / 32, CH / 32, BATCH + 1), dim3(32, 8)>>>(z_e, embed);
    mma_argmin_kernel<<<NPOS / 256, 256, SMEM_TOTAL>>>();
    repair_kernel<<<1024, 256, RP_SMEM>>>(embed);
    zq_kernel<<<BATCH * 16, 256>>>(z_e, embed, out);
}